// round 10
// baseline (speedup 1.0000x reference)
#include <cuda_runtime.h>
#include <cuda_bf16.h>
#include <cstdint>
#include <cstddef>

// ---------------- problem constants ----------------
#define B_SZ   256
#define T_SZ   1024
#define I_SZ   128
#define H_SZ   256
#define CLC    8                 // CTAs per cluster (hidden split)
#define GRID_CTAS 128
#define THREADS2 512             // recurrent kernel: 16 warps, single group
#define NBC    16                // batch rows per cluster

// ---------------- recurrent kernel SMEM ----------------
#define SA2 520                              // 1040B = 65*16B odd -> conflict-free ldmatrix
#define SB2 520
#define A_BYTES2  (128 * SA2 * 2)            // 133120
#define B_OFF2    A_BYTES2
#define B_BYTES2  (NBC * SB2 * 2)            // 16640
#define SCR_OFF2  (B_OFF2 + B_BYTES2)        // 149760
#define SCR_S     20
#define MBAR_OFF  (SCR_OFF2 + 128 * SCR_S * 4)   // 160000
#define SMEM2     (MBAR_OFF + 64)            // 160064

// ---------------- precompute kernel SMEM ----------------
#define SA3 264                              // 528B = 33*16B odd
#define PC_A_BYTES (128 * SA3 * 2)           // 67584 (x tile, M=128)
#define PC_B_BYTES (256 * SA3 * 2)           // 135168 (W tile, N=256)
#define SMEM3 (PC_A_BYTES + PC_B_BYTES)      // 202752

// x-projection scratch: xp[t*B + b][g*256 + h], fp32, 1 GiB
__device__ float g_xproj[268435456];
// packed (hi | lo<<16) bf16 short-state exchange, ping-pong, in L2
__device__ uint32_t g_short_pack[2][B_SZ * H_SZ];
// pre-split, transposed x-weights: [gate][h=256][k=128] packed (hi | lo<<16)
__device__ uint32_t g_wxt[4][256 * 128];

// ---------------- helpers ----------------
__device__ __forceinline__ uint32_t smem_u32(const void* p) {
    uint32_t a;
    asm("{ .reg .u64 t; cvta.to.shared.u64 t, %1; cvt.u32.u64 %0, t; }" : "=r"(a) : "l"(p));
    return a;
}
__device__ __forceinline__ void cluster_sync() {
    asm volatile("barrier.cluster.arrive.aligned;" ::: "memory");
    asm volatile("barrier.cluster.wait.aligned;"   ::: "memory");
}
__device__ __forceinline__ void ldsm4(uint32_t* r, uint32_t addr) {
    asm volatile("ldmatrix.sync.aligned.m8n8.x4.shared.b16 {%0,%1,%2,%3}, [%4];"
                 : "=r"(r[0]), "=r"(r[1]), "=r"(r[2]), "=r"(r[3]) : "r"(addr));
}
__device__ __forceinline__ void ldsm2(uint32_t* r, uint32_t addr) {
    asm volatile("ldmatrix.sync.aligned.m8n8.x2.shared.b16 {%0,%1}, [%2];"
                 : "=r"(r[0]), "=r"(r[1]) : "r"(addr));
}
__device__ __forceinline__ void mma16816(float* d, const uint32_t* a, const uint32_t* b) {
    asm volatile("mma.sync.aligned.m16n8k16.row.col.f32.bf16.bf16.f32 "
                 "{%0,%1,%2,%3}, {%4,%5,%6,%7}, {%8,%9}, {%0,%1,%2,%3};"
                 : "+f"(d[0]), "+f"(d[1]), "+f"(d[2]), "+f"(d[3])
                 : "r"(a[0]), "r"(a[1]), "r"(a[2]), "r"(a[3]), "r"(b[0]), "r"(b[1]));
}
__device__ __forceinline__ void mbar_init(uint32_t mbar, uint32_t cnt) {
    asm volatile("mbarrier.init.shared.b64 [%0], %1;" :: "r"(mbar), "r"(cnt) : "memory");
}
// release.cluster arrive on peer CTA `rank`'s mbarrier (cumulative: orders our
// prior global stores for cluster-scope consumers that acquire on this barrier).
__device__ __forceinline__ void mbar_arrive_release_cluster(uint32_t local_mbar, uint32_t rank) {
    asm volatile("{\n\t.reg .b32 ra;\n\t"
                 "mapa.shared::cluster.u32 ra, %0, %1;\n\t"
                 "mbarrier.arrive.release.cluster.shared::cluster.b64 _, [ra];\n\t}"
                 :: "r"(local_mbar), "r"(rank) : "memory");
}
__device__ __forceinline__ void mbar_wait_parity(uint32_t mbar, uint32_t parity) {
    asm volatile("{\n\t.reg .pred P1;\n\t"
                 "WAIT_LOOP_%=:\n\t"
                 "mbarrier.try_wait.parity.acquire.cluster.shared::cta.b64 P1, [%0], %1, 0x989680;\n\t"
                 "@P1 bra.uni WAIT_DONE_%=;\n\t"
                 "bra.uni WAIT_LOOP_%=;\n\t"
                 "WAIT_DONE_%=:\n\t}" :: "r"(mbar), "r"(parity) : "memory");
}
__device__ __forceinline__ float sigm(float x) {
    return __fdividef(1.0f, 1.0f + __expf(-x));
}
__device__ __forceinline__ float tanh_(float x) {
    float e = __expf(-2.0f * fabsf(x));
    return copysignf(__fdividef(1.0f - e, 1.0f + e), x);
}
__device__ __forceinline__ void split_bf16(float v, __nv_bfloat16& hi, __nv_bfloat16& lo) {
    hi = __float2bfloat16_rn(v);
    lo = __float2bfloat16_rn(v - __bfloat162float(hi));
}

// ================= wsplit: Wx -> split/transposed packed global =================
__global__ void __launch_bounds__(256)
wsplit_kernel(const float* __restrict__ Wf_x, const float* __restrict__ Wip_x,
              const float* __restrict__ Wit_x, const float* __restrict__ Wo_x)
{
    const int g = blockIdx.x >> 5;
    const int chunk = blockIdx.x & 31;
    const float* W = (g == 0) ? Wf_x : (g == 1) ? Wip_x : (g == 2) ? Wit_x : Wo_x;
    const int i = chunk * 1024 + threadIdx.x * 4;
    #pragma unroll
    for (int q = 0; q < 4; q++) {
        const int n = (i + q) >> 7, k = (i + q) & 127;
        float v = W[(size_t)k * H_SZ + n];
        __nv_bfloat16 hi, lo;
        split_bf16(v, hi, lo);
        g_wxt[g][i + q] = (uint32_t)__bfloat16_as_ushort(hi) |
                          ((uint32_t)__bfloat16_as_ushort(lo) << 16);
    }
}

// ================= precompute: xp = x @ Wx ; block = (t, batch-half) x gate, N=256 =================
__global__ void __launch_bounds__(256, 1)
xproj_kernel(const float* __restrict__ x)
{
    extern __shared__ char smem[];
    __nv_bfloat16* Ax = (__nv_bfloat16*)smem;                  // [128][264] hi|lo
    __nv_bfloat16* Bw = (__nv_bfloat16*)(smem + PC_A_BYTES);   // [256][264] hi|lo

    const int tid = threadIdx.x;
    const int w   = tid >> 5;
    const int l   = tid & 31;
    const int t   = blockIdx.x >> 1;
    const int bh  = (blockIdx.x & 1) * 128;
    const int g   = blockIdx.y;

    {
        const int r    = tid >> 1;
        const int half = (tid & 1) * 64;
        const float* xr = x + ((size_t)(bh + r) * T_SZ + t) * I_SZ + half;
        #pragma unroll 4
        for (int q = 0; q < 64; q++) {
            __nv_bfloat16 hi, lo;
            split_bf16(xr[q], hi, lo);
            Ax[r * SA3 + half + q]       = hi;
            Ax[r * SA3 + 128 + half + q] = lo;
        }
    }
    {
        const uint32_t* src = g_wxt[g] + (size_t)tid * 128;
        #pragma unroll 4
        for (int q = 0; q < 128; q += 2) {
            uint32_t u0 = __ldcg(src + q), u1 = __ldcg(src + q + 1);
            *(uint32_t*)&Bw[tid * SA3 + q]       = (u0 & 0xffffu) | (u1 << 16);
            *(uint32_t*)&Bw[tid * SA3 + 128 + q] = (u0 >> 16) | (u1 & 0xffff0000u);
        }
    }
    __syncthreads();

    const uint32_t a_lane = smem_u32(Ax) +
        (uint32_t)(((16 * w + (l & 7) + 8 * ((l >> 3) & 1)) * SA3 + 8 * (l >> 4)) * 2);
    const uint32_t b_lane = smem_u32(Bw) +
        (uint32_t)((((l & 7) + 8 * (l >> 4)) * SA3 + 8 * ((l >> 3) & 1)) * 2);

    float acc[32][4];
    #pragma unroll
    for (int i = 0; i < 32; i++)
        #pragma unroll
        for (int j = 0; j < 4; j++) acc[i][j] = 0.0f;

    #pragma unroll 1
    for (int kc = 0; kc < 8; kc++) {
        uint32_t ah[4], al[4];
        ldsm4(ah, a_lane + kc * 32);
        ldsm4(al, a_lane + 256 + kc * 32);
        #pragma unroll
        for (int nt = 0; nt < 16; nt++) {
            uint32_t bh4[4], bl4[4];
            uint32_t ba = b_lane + (uint32_t)(nt * 16 * SA3 * 2) + kc * 32;
            ldsm4(bh4, ba);
            ldsm4(bl4, ba + 256);
            mma16816(acc[2 * nt],     ah, bh4 + 0);
            mma16816(acc[2 * nt + 1], ah, bh4 + 2);
            mma16816(acc[2 * nt],     al, bh4 + 0);
            mma16816(acc[2 * nt + 1], al, bh4 + 2);
            mma16816(acc[2 * nt],     ah, bl4 + 0);
            mma16816(acc[2 * nt + 1], ah, bl4 + 2);
        }
    }

    {
        const size_t row0 = (size_t)t * B_SZ + bh + 16 * w + (l >> 2);
        const int    cb   = g * 256 + (l & 3) * 2;
        #pragma unroll
        for (int nt = 0; nt < 16; nt++) {
            *(float2*)&g_xproj[row0 * 1024 + cb + nt * 16]           = make_float2(acc[2*nt][0], acc[2*nt][1]);
            *(float2*)&g_xproj[(row0 + 8) * 1024 + cb + nt * 16]     = make_float2(acc[2*nt][2], acc[2*nt][3]);
            *(float2*)&g_xproj[row0 * 1024 + cb + nt * 16 + 8]       = make_float2(acc[2*nt+1][0], acc[2*nt+1][1]);
            *(float2*)&g_xproj[(row0 + 8) * 1024 + cb + nt * 16 + 8] = make_float2(acc[2*nt+1][2], acc[2*nt+1][3]);
        }
    }
}

// ================= recurrent kernel: single pipeline, 16 warps (8 M-tiles x 2 N-halves) =================
__global__ void __launch_bounds__(THREADS2, 1) __cluster_dims__(CLC, 1, 1)
lstm_rec_kernel(const float* __restrict__ Wf_h,  const float* __restrict__ bf,
                const float* __restrict__ Wip_h, const float* __restrict__ bip,
                const float* __restrict__ Wit_h, const float* __restrict__ bit_,
                const float* __restrict__ Wo_h,  const float* __restrict__ bo,
                float* __restrict__ out)
{
    extern __shared__ char smem[];
    __nv_bfloat16* As = (__nv_bfloat16*)smem;
    float* scr = (float*)(smem + SCR_OFF2);   // [128][20]
    const uint32_t sb = smem_u32(smem);

    const int tid = threadIdx.x;
    const int w   = tid >> 5;
    const int l   = tid & 31;
    const int wl  = w & 7;                   // M-tile
    const int wn  = w >> 3;                  // N-half (batches 8wn..8wn+7)
    const int cc  = blockIdx.x & (CLC - 1);
    const int grp = blockIdx.x >> 3;
    const int b0  = grp * NBC;

    if (tid == 0) mbar_init(sb + MBAR_OFF, CLC);

    // ---- stage A (short-part weights, K=256) hi|lo ----
    {
        const int r  = tid >> 2;
        const int kq = (tid & 3) * 64;
        const int g  = r & 3;
        const int hs = 32 * cc + (r >> 2);
        const float* Wh = (g == 0) ? Wf_h : (g == 1) ? Wip_h : (g == 2) ? Wit_h : Wo_h;
        #pragma unroll 4
        for (int k = kq; k < kq + 64; k++) {
            __nv_bfloat16 hi, lo;
            split_bf16(Wh[(size_t)k * H_SZ + hs], hi, lo);
            As[r * SA2 + k]       = hi;
            As[r * SA2 + 256 + k] = lo;
        }
    }
    // ---- zero step-0 short buffer (own slice: 16 rows x 32 h) ----
    {
        const int rz = tid >> 5, hz = tid & 31;
        __stcg(&g_short_pack[0][(size_t)(b0 + rz) * H_SZ + 32 * cc + hz], 0u);
    }
    __syncthreads();

    // ---- A-hi frags to registers (once); A-lo stays in SMEM ----
    const uint32_t a_lane = sb +
        (uint32_t)(((16 * wl + (l & 7) + 8 * ((l >> 3) & 1)) * SA2 + 8 * (l >> 4)) * 2);
    uint32_t ahf[16][4];
    #pragma unroll
    for (int kc = 0; kc < 16; kc++) ldsm4(ahf[kc], a_lane + kc * 32);

    const uint32_t b_lane = sb + B_OFF2 +
        (uint32_t)(((8 * wn + (l & 7)) * SB2 + ((l >> 3) & 1) * 8) * 2);
    const uint32_t mbar = sb + MBAR_OFF;

    // ---- epilogue mapping: 1 cell per thread (hl = tid>>4, bb = tid&15) ----
    const int hl = tid >> 4;
    const int bb = tid & 15;
    const int hg = 32 * cc + hl;
    const float biasv[4] = {bf[hg], bip[hg], bit_[hg], bo[hg]};
    float longv = 0.0f;

    __threadfence();
    __syncthreads();
    cluster_sync();

    #pragma unroll 1
    for (int t = 0; t < T_SZ; t++) {
        const int cur = t & 1;
        const int nxt = cur ^ 1;

        // prefetch x-projection (t-dependent only; issued before the wait)
        float xpv[4];
        {
            const float* xr = g_xproj + ((size_t)t * B_SZ + b0 + bb) * 1024 + hg;
            #pragma unroll
            for (int g = 0; g < 4; g++) xpv[g] = __ldcg(xr + g * 256);
        }

        // wait for all 8 CTAs' step-t short state
        if (t > 0) mbar_wait_parity(mbar, (t - 1) & 1);

        // ===== stage B tile [16 rows][256 h] from L2 =====
        {
            const int row = tid >> 5;
            const int hb8 = (tid & 31) * 8;
            const uint32_t* srow = g_short_pack[cur] + (size_t)(b0 + row) * H_SZ + hb8;
            uint4 v0 = __ldcg((const uint4*)srow);
            uint4 v1 = __ldcg((const uint4*)(srow + 4));
            __nv_bfloat16* brow = (__nv_bfloat16*)(smem + B_OFF2) + row * SB2;
            *(uint2*)&brow[hb8]           = make_uint2(__byte_perm(v0.x, v0.y, 0x5410),
                                                       __byte_perm(v0.z, v0.w, 0x5410));
            *(uint2*)&brow[hb8 + 4]       = make_uint2(__byte_perm(v1.x, v1.y, 0x5410),
                                                       __byte_perm(v1.z, v1.w, 0x5410));
            *(uint2*)&brow[256 + hb8]     = make_uint2(__byte_perm(v0.x, v0.y, 0x7632),
                                                       __byte_perm(v0.z, v0.w, 0x7632));
            *(uint2*)&brow[256 + hb8 + 4] = make_uint2(__byte_perm(v1.x, v1.y, 0x7632),
                                                       __byte_perm(v1.z, v1.w, 0x7632));
        }
        __syncthreads();

        // ===== GEMM: M=128, N=8 (this half), K=256; 3 independent chains =====
        float acc0[4] = {0.f, 0.f, 0.f, 0.f};   // Ahi * Bhi
        float acc1[4] = {0.f, 0.f, 0.f, 0.f};   // Alo * Bhi
        float acc2[4] = {0.f, 0.f, 0.f, 0.f};   // Ahi * Blo
        #pragma unroll
        for (int kc = 0; kc < 16; kc++) {
            uint32_t bh2[2], bl2[2], alo[4];
            const uint32_t kb = (uint32_t)kc * 32;
            ldsm2(bh2, b_lane + kb);
            ldsm2(bl2, b_lane + 512 + kb);
            ldsm4(alo, a_lane + 512 + kb);
            mma16816(acc0, ahf[kc], bh2);
            mma16816(acc1, alo,     bh2);
            mma16816(acc2, ahf[kc], bl2);
        }

        // ===== partials -> scratch =====
        {
            const int r0 = 16 * wl + (l >> 2);
            const int c0 = 8 * wn + (l & 3) * 2;
            *(float2*)&scr[r0 * SCR_S + c0]       = make_float2(acc0[0] + acc1[0] + acc2[0],
                                                                acc0[1] + acc1[1] + acc2[1]);
            *(float2*)&scr[(r0 + 8) * SCR_S + c0] = make_float2(acc0[2] + acc1[2] + acc2[2],
                                                                acc0[3] + acc1[3] + acc2[3]);
        }
        __syncthreads();

        // ===== epilogue: 1 cell (hl, bb) =====
        {
            float z[4];
            #pragma unroll
            for (int g = 0; g < 4; g++)
                z[g] = scr[(4 * hl + g) * SCR_S + bb] + xpv[g] + biasv[g];
            float f  = sigm(z[0]);
            float ip = sigm(z[1]);
            float pt = tanh_(z[2]);
            longv = f * longv + ip * pt;
            float o  = sigm(z[3]);
            float ns = tanh_(longv) * o;

            __nv_bfloat16 hi, lo;
            split_bf16(ns, hi, lo);
            uint32_t pk = (uint32_t)__bfloat16_as_ushort(hi) |
                          ((uint32_t)__bfloat16_as_ushort(lo) << 16);
            const int bbg = b0 + bb;
            __stcg(&g_short_pack[nxt][(size_t)bbg * H_SZ + hg], pk);

            if (t == T_SZ - 1) {
                out[(size_t)bbg * H_SZ + hg]                       = ns;
                out[(size_t)B_SZ * H_SZ + (size_t)bbg * H_SZ + hg] = longv;
            }
        }
        __syncthreads();

        // publish: release.cluster arrives, one per peer rank, threads 0-7 in parallel
        if (tid < CLC && t < T_SZ - 1)
            mbar_arrive_release_cluster(mbar, (uint32_t)tid);
    }
    cluster_sync();  // keep SMEM alive for in-flight remote arrives
}

// ---------------- launch ----------------
extern "C" void kernel_launch(void* const* d_in, const int* in_sizes, int n_in,
                              void* d_out, int out_size)
{
    (void)in_sizes; (void)n_in; (void)out_size;
    const float* x     = (const float*)d_in[0];
    const float* Wf_h  = (const float*)d_in[1];
    const float* Wf_x  = (const float*)d_in[2];
    const float* bf    = (const float*)d_in[3];
    const float* Wip_h = (const float*)d_in[4];
    const float* Wip_x = (const float*)d_in[5];
    const float* bip   = (const float*)d_in[6];
    const float* Wit_h = (const float*)d_in[7];
    const float* Wit_x = (const float*)d_in[8];
    const float* bit_  = (const float*)d_in[9];
    const float* Wo_h  = (const float*)d_in[10];
    const float* Wo_x  = (const float*)d_in[11];
    const float* bo    = (const float*)d_in[12];
    float* out = (float*)d_out;

    cudaFuncSetAttribute(xproj_kernel,
                         cudaFuncAttributeMaxDynamicSharedMemorySize, SMEM3);
    cudaFuncSetAttribute(lstm_rec_kernel,
                         cudaFuncAttributeMaxDynamicSharedMemorySize, SMEM2);

    wsplit_kernel<<<128, 256>>>(Wf_x, Wip_x, Wit_x, Wo_x);

    dim3 pgrid(2048, 4);
    xproj_kernel<<<pgrid, 256, SMEM3>>>(x);

    lstm_rec_kernel<<<GRID_CTAS, THREADS2, SMEM2>>>(
        Wf_h, bf, Wip_h, bip, Wit_h, bit_, Wo_h, bo, out);
}

// round 11
// speedup vs baseline: 1.1097x; 1.1097x over previous
#include <cuda_runtime.h>
#include <cuda_bf16.h>
#include <cstdint>
#include <cstddef>

// ---------------- problem constants ----------------
#define B_SZ   256
#define T_SZ   1024
#define I_SZ   128
#define H_SZ   256
#define CLC    8                 // CTAs per cluster (hidden split)
#define GRID_CTAS 128
#define THREADS2 512             // recurrent kernel: 16 warps = 2 groups
#define NBG    8                 // batch rows per group

// ---------------- recurrent kernel SMEM ----------------
#define SA2 520                              // 1040B = 65*16B odd -> conflict-free ldmatrix
#define SB2 520
#define A_BYTES2  (128 * SA2 * 2)            // 133120
#define B_OFF2    A_BYTES2
#define BG_BYTES  (NBG * SB2 * 2)            // 8320 per group tile
#define MBAR_OFF  (B_OFF2 + 2 * BG_BYTES)    // 149760
#define SMEM2     (MBAR_OFF + 64)            // 149824

// ---------------- precompute kernel SMEM ----------------
#define SA3 264                              // 528B = 33*16B odd
#define PC_A_BYTES (128 * SA3 * 2)           // 67584 (x tile, M=128)
#define PC_B_BYTES (256 * SA3 * 2)           // 135168 (W tile, N=256)
#define SMEM3 (PC_A_BYTES + PC_B_BYTES)      // 202752

// x-projection scratch: xp[t*B + b][g*256 + h], fp32, 1 GiB
__device__ float g_xproj[268435456];
// packed (hi | lo<<16) bf16 short-state exchange, ping-pong, in L2
__device__ uint32_t g_short_pack[2][B_SZ * H_SZ];
// pre-split, transposed x-weights: [gate][h=256][k=128] packed (hi | lo<<16)
__device__ uint32_t g_wxt[4][256 * 128];

// ---------------- helpers ----------------
__device__ __forceinline__ uint32_t smem_u32(const void* p) {
    uint32_t a;
    asm("{ .reg .u64 t; cvta.to.shared.u64 t, %1; cvt.u32.u64 %0, t; }" : "=r"(a) : "l"(p));
    return a;
}
__device__ __forceinline__ void cluster_sync() {
    asm volatile("barrier.cluster.arrive.aligned;" ::: "memory");
    asm volatile("barrier.cluster.wait.aligned;"   ::: "memory");
}
__device__ __forceinline__ void bar_named(int id, int cnt) {
    asm volatile("bar.sync %0, %1;" :: "r"(id), "r"(cnt) : "memory");
}
__device__ __forceinline__ void ldsm4(uint32_t* r, uint32_t addr) {
    asm volatile("ldmatrix.sync.aligned.m8n8.x4.shared.b16 {%0,%1,%2,%3}, [%4];"
                 : "=r"(r[0]), "=r"(r[1]), "=r"(r[2]), "=r"(r[3]) : "r"(addr));
}
__device__ __forceinline__ void ldsm2(uint32_t* r, uint32_t addr) {
    asm volatile("ldmatrix.sync.aligned.m8n8.x2.shared.b16 {%0,%1}, [%2];"
                 : "=r"(r[0]), "=r"(r[1]) : "r"(addr));
}
__device__ __forceinline__ void mma16816(float* d, const uint32_t* a, const uint32_t* b) {
    asm volatile("mma.sync.aligned.m16n8k16.row.col.f32.bf16.bf16.f32 "
                 "{%0,%1,%2,%3}, {%4,%5,%6,%7}, {%8,%9}, {%0,%1,%2,%3};"
                 : "+f"(d[0]), "+f"(d[1]), "+f"(d[2]), "+f"(d[3])
                 : "r"(a[0]), "r"(a[1]), "r"(a[2]), "r"(a[3]), "r"(b[0]), "r"(b[1]));
}
__device__ __forceinline__ void mbar_init(uint32_t mbar, uint32_t cnt) {
    asm volatile("mbarrier.init.shared.b64 [%0], %1;" :: "r"(mbar), "r"(cnt) : "memory");
}
__device__ __forceinline__ void mbar_arrive_cluster(uint32_t local_mbar, uint32_t rank) {
    asm volatile("{\n\t.reg .b32 ra;\n\t"
                 "mapa.shared::cluster.u32 ra, %0, %1;\n\t"
                 "mbarrier.arrive.shared::cluster.b64 _, [ra];\n\t}"
                 :: "r"(local_mbar), "r"(rank) : "memory");
}
__device__ __forceinline__ void mbar_wait_parity(uint32_t mbar, uint32_t parity) {
    asm volatile("{\n\t.reg .pred P1;\n\t"
                 "WAIT_LOOP_%=:\n\t"
                 "mbarrier.try_wait.parity.acquire.cluster.shared::cta.b64 P1, [%0], %1, 0x989680;\n\t"
                 "@P1 bra.uni WAIT_DONE_%=;\n\t"
                 "bra.uni WAIT_LOOP_%=;\n\t"
                 "WAIT_DONE_%=:\n\t}" :: "r"(mbar), "r"(parity) : "memory");
}
// HW tanh (MUFU.TANH): abs err ~2^-11; per-step injection strongly damped by the
// recurrence (measured: bf16 injection 7.6e-6/step -> 2.6e-7 total).
__device__ __forceinline__ float tanhap(float x) {
    float y; asm("tanh.approx.f32 %0, %1;" : "=f"(y) : "f"(x)); return y;
}
__device__ __forceinline__ float sigap(float x) {
    return fmaf(0.5f, tanhap(0.5f * x), 0.5f);
}
__device__ __forceinline__ void split_bf16(float v, __nv_bfloat16& hi, __nv_bfloat16& lo) {
    hi = __float2bfloat16_rn(v);
    lo = __float2bfloat16_rn(v - __bfloat162float(hi));
}

// ================= wsplit: Wx -> split/transposed packed global =================
__global__ void __launch_bounds__(256)
wsplit_kernel(const float* __restrict__ Wf_x, const float* __restrict__ Wip_x,
              const float* __restrict__ Wit_x, const float* __restrict__ Wo_x)
{
    const int g = blockIdx.x >> 5;
    const int chunk = blockIdx.x & 31;
    const float* W = (g == 0) ? Wf_x : (g == 1) ? Wip_x : (g == 2) ? Wit_x : Wo_x;
    const int i = chunk * 1024 + threadIdx.x * 4;
    #pragma unroll
    for (int q = 0; q < 4; q++) {
        const int n = (i + q) >> 7, k = (i + q) & 127;
        float v = W[(size_t)k * H_SZ + n];
        __nv_bfloat16 hi, lo;
        split_bf16(v, hi, lo);
        g_wxt[g][i + q] = (uint32_t)__bfloat16_as_ushort(hi) |
                          ((uint32_t)__bfloat16_as_ushort(lo) << 16);
    }
}

// ================= precompute: xp = x @ Wx ; block = (t, batch-half) x gate, N=256 =================
__global__ void __launch_bounds__(256, 1)
xproj_kernel(const float* __restrict__ x)
{
    extern __shared__ char smem[];
    __nv_bfloat16* Ax = (__nv_bfloat16*)smem;                  // [128][264] hi|lo
    __nv_bfloat16* Bw = (__nv_bfloat16*)(smem + PC_A_BYTES);   // [256][264] hi|lo

    const int tid = threadIdx.x;
    const int w   = tid >> 5;
    const int l   = tid & 31;
    const int t   = blockIdx.x >> 1;
    const int bh  = (blockIdx.x & 1) * 128;
    const int g   = blockIdx.y;

    {
        const int r    = tid >> 1;
        const int half = (tid & 1) * 64;
        const float* xr = x + ((size_t)(bh + r) * T_SZ + t) * I_SZ + half;
        #pragma unroll 4
        for (int q = 0; q < 64; q++) {
            __nv_bfloat16 hi, lo;
            split_bf16(xr[q], hi, lo);
            Ax[r * SA3 + half + q]       = hi;
            Ax[r * SA3 + 128 + half + q] = lo;
        }
    }
    {
        const uint32_t* src = g_wxt[g] + (size_t)tid * 128;
        #pragma unroll 4
        for (int q = 0; q < 128; q += 2) {
            uint32_t u0 = __ldcg(src + q), u1 = __ldcg(src + q + 1);
            *(uint32_t*)&Bw[tid * SA3 + q]       = (u0 & 0xffffu) | (u1 << 16);
            *(uint32_t*)&Bw[tid * SA3 + 128 + q] = (u0 >> 16) | (u1 & 0xffff0000u);
        }
    }
    __syncthreads();

    const uint32_t a_lane = smem_u32(Ax) +
        (uint32_t)(((16 * w + (l & 7) + 8 * ((l >> 3) & 1)) * SA3 + 8 * (l >> 4)) * 2);
    const uint32_t b_lane = smem_u32(Bw) +
        (uint32_t)((((l & 7) + 8 * (l >> 4)) * SA3 + 8 * ((l >> 3) & 1)) * 2);

    float acc[32][4];
    #pragma unroll
    for (int i = 0; i < 32; i++)
        #pragma unroll
        for (int j = 0; j < 4; j++) acc[i][j] = 0.0f;

    #pragma unroll 1
    for (int kc = 0; kc < 8; kc++) {
        uint32_t ah[4], al[4];
        ldsm4(ah, a_lane + kc * 32);
        ldsm4(al, a_lane + 256 + kc * 32);
        #pragma unroll
        for (int nt = 0; nt < 16; nt++) {
            uint32_t bh4[4], bl4[4];
            uint32_t ba = b_lane + (uint32_t)(nt * 16 * SA3 * 2) + kc * 32;
            ldsm4(bh4, ba);
            ldsm4(bl4, ba + 256);
            mma16816(acc[2 * nt],     ah, bh4 + 0);
            mma16816(acc[2 * nt + 1], ah, bh4 + 2);
            mma16816(acc[2 * nt],     al, bh4 + 0);
            mma16816(acc[2 * nt + 1], al, bh4 + 2);
            mma16816(acc[2 * nt],     ah, bl4 + 0);
            mma16816(acc[2 * nt + 1], ah, bl4 + 2);
        }
    }

    {
        const size_t row0 = (size_t)t * B_SZ + bh + 16 * w + (l >> 2);
        const int    cb   = g * 256 + (l & 3) * 2;
        #pragma unroll
        for (int nt = 0; nt < 16; nt++) {
            *(float2*)&g_xproj[row0 * 1024 + cb + nt * 16]           = make_float2(acc[2*nt][0], acc[2*nt][1]);
            *(float2*)&g_xproj[(row0 + 8) * 1024 + cb + nt * 16]     = make_float2(acc[2*nt][2], acc[2*nt][3]);
            *(float2*)&g_xproj[row0 * 1024 + cb + nt * 16 + 8]       = make_float2(acc[2*nt+1][0], acc[2*nt+1][1]);
            *(float2*)&g_xproj[(row0 + 8) * 1024 + cb + nt * 16 + 8] = make_float2(acc[2*nt+1][2], acc[2*nt+1][3]);
        }
    }
}

// ================= recurrent kernel: 2 warp-specialized groups, in-register epilogue =================
__global__ void __launch_bounds__(THREADS2, 1) __cluster_dims__(CLC, 1, 1)
lstm_rec_kernel(const float* __restrict__ Wf_h,  const float* __restrict__ bf,
                const float* __restrict__ Wip_h, const float* __restrict__ bip,
                const float* __restrict__ Wit_h, const float* __restrict__ bit_,
                const float* __restrict__ Wo_h,  const float* __restrict__ bo,
                float* __restrict__ out)
{
    extern __shared__ char smem[];
    __nv_bfloat16* As = (__nv_bfloat16*)smem;
    const uint32_t sb = smem_u32(smem);

    const int tid  = threadIdx.x;
    const int w    = tid >> 5;
    const int l    = tid & 31;
    const int wg   = w >> 3;                 // group 0/1
    const int wl   = w & 7;                  // M-tile within group
    const int tidg = tid & 255;              // thread id within group
    const int cc   = blockIdx.x & (CLC - 1);
    const int grp  = blockIdx.x >> 3;
    const int b0   = grp * 16;
    const int gb   = b0 + wg * NBG;          // group batch base

    if (tid == 0) { mbar_init(sb + MBAR_OFF, CLC); mbar_init(sb + MBAR_OFF + 8, CLC); }

    // ---- stage A (short-part weights, K=256) hi|lo ----
    {
        const int r  = tid >> 2;             // row = 4*h_local + gate
        const int kq = (tid & 3) * 64;
        const int g  = r & 3;
        const int hs = 32 * cc + (r >> 2);
        const float* Wh = (g == 0) ? Wf_h : (g == 1) ? Wip_h : (g == 2) ? Wit_h : Wo_h;
        #pragma unroll 4
        for (int k = kq; k < kq + 64; k++) {
            __nv_bfloat16 hi, lo;
            split_bf16(Wh[(size_t)k * H_SZ + hs], hi, lo);
            As[r * SA2 + k]       = hi;
            As[r * SA2 + 256 + k] = lo;
        }
    }
    // ---- zero step-0 short buffer (own slice) ----
    {
        const int gz = tid >> 8, rz = (tid >> 5) & 7, hz = tid & 31;
        __stcg(&g_short_pack[0][(size_t)(b0 + gz * NBG + rz) * H_SZ + 32 * cc + hz], 0u);
    }
    __syncthreads();

    // ---- A-hi frags to registers (once); A-lo stays in SMEM ----
    const uint32_t a_lane = sb +
        (uint32_t)(((16 * wl + (l & 7) + 8 * ((l >> 3) & 1)) * SA2 + 8 * (l >> 4)) * 2);
    uint32_t ahf[16][4];
    #pragma unroll
    for (int kc = 0; kc < 16; kc++) ldsm4(ahf[kc], a_lane + kc * 32);

    const uint32_t bsbase = sb + B_OFF2 + (uint32_t)wg * BG_BYTES;
    const uint32_t b_lane = bsbase + (uint32_t)(((l & 7) * SB2 + ((l >> 3) & 1) * 8) * 2);
    const uint32_t mbar = sb + MBAR_OFF + wg * 8;
    const int barid = wg + 1;

    // ---- in-register epilogue mapping: lane owns cell (h_loc, bq) ----
    const int h_loc = l >> 3;                // 0..3 within warp
    const int bq    = l & 7;                 // batch within group
    const int hg    = 32 * cc + 4 * wl + h_loc;
    const float biasv[4] = {bf[hg], bip[hg], bit_[hg], bo[hg]};
    float longv = 0.0f;

    __threadfence();
    __syncthreads();
    cluster_sync();

    #pragma unroll 1
    for (int t = 0; t < T_SZ; t++) {
        const int cur = t & 1;
        const int nxt = cur ^ 1;

        // prefetch x-projection for this lane's cell (issued before the wait)
        float xpv[4];
        {
            const float* xr = g_xproj + ((size_t)t * B_SZ + gb + bq) * 1024 + hg;
            #pragma unroll
            for (int g = 0; g < 4; g++) xpv[g] = __ldcg(xr + g * 256);
        }

        // wait for peers' step-t short state
        if (t > 0) mbar_wait_parity(mbar, (t - 1) & 1);

        // ===== stage B tile [8 rows][256 h] from L2 =====
        {
            const int row = tidg >> 5;
            const int hb8 = (tidg & 31) * 8;
            const uint32_t* srow = g_short_pack[cur] + (size_t)(gb + row) * H_SZ + hb8;
            uint4 v0 = __ldcg((const uint4*)srow);
            uint4 v1 = __ldcg((const uint4*)(srow + 4));
            __nv_bfloat16* brow = (__nv_bfloat16*)(smem + B_OFF2 + wg * BG_BYTES) + row * SB2;
            *(uint2*)&brow[hb8]           = make_uint2(__byte_perm(v0.x, v0.y, 0x5410),
                                                       __byte_perm(v0.z, v0.w, 0x5410));
            *(uint2*)&brow[hb8 + 4]       = make_uint2(__byte_perm(v1.x, v1.y, 0x5410),
                                                       __byte_perm(v1.z, v1.w, 0x5410));
            *(uint2*)&brow[256 + hb8]     = make_uint2(__byte_perm(v0.x, v0.y, 0x7632),
                                                       __byte_perm(v0.z, v0.w, 0x7632));
            *(uint2*)&brow[256 + hb8 + 4] = make_uint2(__byte_perm(v1.x, v1.y, 0x7632),
                                                       __byte_perm(v1.z, v1.w, 0x7632));
        }
        bar_named(barid, 256);

        // ===== GEMM: M=128, N=8, K=256; A-hi in regs; 3 independent chains =====
        float acc0[4] = {0.f, 0.f, 0.f, 0.f};   // Ahi*Bhi
        float acc1[4] = {0.f, 0.f, 0.f, 0.f};   // Alo*Bhi
        float acc2[4] = {0.f, 0.f, 0.f, 0.f};   // Ahi*Blo
        #pragma unroll
        for (int kc = 0; kc < 16; kc++) {
            uint32_t bh2[2], bl2[2], alo[4];
            const uint32_t kb = (uint32_t)kc * 32;
            ldsm2(bh2, b_lane + kb);
            ldsm2(bl2, b_lane + 512 + kb);
            ldsm4(alo, a_lane + 512 + kb);
            mma16816(acc0, ahf[kc], bh2);
            mma16816(acc1, alo,     bh2);
            mma16816(acc2, ahf[kc], bl2);
        }
        const float s0 = acc0[0] + acc1[0] + acc2[0];
        const float s1 = acc0[1] + acc1[1] + acc2[1];
        const float s2 = acc0[2] + acc1[2] + acc2[2];
        const float s3 = acc0[3] + acc1[3] + acc2[3];

        // ===== shfl-gather the 4 gate values for this lane's (h_loc, bq) =====
        // frag cell: rows l>>2 (c0,c1) and (l>>2)+8 (c2,c3), cols 2(l&3), 2(l&3)+1
        float z[4];
        #pragma unroll
        for (int g = 0; g < 4; g++) {
            const int row  = 4 * h_loc + g;              // 0..15
            const int srcl = ((row & 7) << 2) | (bq >> 1);
            float t0 = __shfl_sync(0xffffffffu, s0, srcl);
            float t1 = __shfl_sync(0xffffffffu, s1, srcl);
            float t2 = __shfl_sync(0xffffffffu, s2, srcl);
            float t3 = __shfl_sync(0xffffffffu, s3, srcl);
            float lo = (bq & 1) ? t1 : t0;
            float hi = (bq & 1) ? t3 : t2;
            z[g] = (h_loc < 2) ? lo : hi;
        }

        // ===== in-register epilogue =====
        {
            #pragma unroll
            for (int g = 0; g < 4; g++) z[g] += xpv[g] + biasv[g];
            float f  = sigap(z[0]);
            float ip = sigap(z[1]);
            float pt = tanhap(z[2]);
            longv = f * longv + ip * pt;
            float o  = sigap(z[3]);
            float ns = tanhap(longv) * o;

            __nv_bfloat16 hi, lo;
            split_bf16(ns, hi, lo);
            uint32_t pk = (uint32_t)__bfloat16_as_ushort(hi) |
                          ((uint32_t)__bfloat16_as_ushort(lo) << 16);
            const int bbg = gb + bq;
            __stcg(&g_short_pack[nxt][(size_t)bbg * H_SZ + hg], pk);

            if (t == T_SZ - 1) {
                out[(size_t)bbg * H_SZ + hg]                       = ns;
                out[(size_t)B_SZ * H_SZ + (size_t)bbg * H_SZ + hg] = longv;
            }
        }
        bar_named(barid, 256);

        // publish: one gpu-scope fence + remote arrives (tid 0 of group)
        if (tidg == 0 && t < T_SZ - 1) {
            asm volatile("fence.acq_rel.gpu;" ::: "memory");
            #pragma unroll
            for (int d = 0; d < CLC; d++) mbar_arrive_cluster(mbar, d);
        }
    }
    cluster_sync();  // keep SMEM alive for in-flight remote arrives
}

// ---------------- launch ----------------
extern "C" void kernel_launch(void* const* d_in, const int* in_sizes, int n_in,
                              void* d_out, int out_size)
{
    (void)in_sizes; (void)n_in; (void)out_size;
    const float* x     = (const float*)d_in[0];
    const float* Wf_h  = (const float*)d_in[1];
    const float* Wf_x  = (const float*)d_in[2];
    const float* bf    = (const float*)d_in[3];
    const float* Wip_h = (const float*)d_in[4];
    const float* Wip_x = (const float*)d_in[5];
    const float* bip   = (const float*)d_in[6];
    const float* Wit_h = (const float*)d_in[7];
    const float* Wit_x = (const float*)d_in[8];
    const float* bit_  = (const float*)d_in[9];
    const float* Wo_h  = (const float*)d_in[10];
    const float* Wo_x  = (const float*)d_in[11];
    const float* bo    = (const float*)d_in[12];
    float* out = (float*)d_out;

    cudaFuncSetAttribute(xproj_kernel,
                         cudaFuncAttributeMaxDynamicSharedMemorySize, SMEM3);
    cudaFuncSetAttribute(lstm_rec_kernel,
                         cudaFuncAttributeMaxDynamicSharedMemorySize, SMEM2);

    wsplit_kernel<<<128, 256>>>(Wf_x, Wip_x, Wit_x, Wo_x);

    dim3 pgrid(2048, 4);
    xproj_kernel<<<pgrid, 256, SMEM3>>>(x);

    lstm_rec_kernel<<<GRID_CTAS, THREADS2, SMEM2>>>(
        Wf_h, bf, Wip_h, bip, Wit_h, bit_, Wo_h, bo, out);
}